// round 2
// baseline (speedup 1.0000x reference)
#include <cuda_runtime.h>
#include <math.h>

#define NN 100000
#define EE 1000000
#define DH 64
#define DIN 128
#define DOUT 40
#define LL 7

// ---------------- scratch (static device memory; no allocs) ----------------
__device__ float  g_bufA[(size_t)NN * DH];
__device__ float  g_bufB[(size_t)NN * DH];
__device__ float  g_bufU[(size_t)NN * DH];
__device__ int    g_counts[NN];
__device__ int    g_row_off[NN + 1];
__device__ int    g_cursor[NN];
__device__ int    g_csr_src[EE];
__device__ double g_sum[DH];
__device__ double g_sumsq[DH];
__device__ float  g_aff_a[DH];
__device__ float  g_aff_b[DH];

// ---------------- CSR build ----------------
__global__ void zero_counts_kernel() {
    int i = blockIdx.x * blockDim.x + threadIdx.x;
    if (i < NN) g_counts[i] = 0;
}

__global__ void count_kernel(const int* __restrict__ dstp) {
    int i = blockIdx.x * blockDim.x + threadIdx.x;
    if (i < EE) atomicAdd(&g_counts[dstp[i]], 1);
}

__global__ void scan_kernel() {
    __shared__ int ssum[1024];
    const int t = threadIdx.x;
    const int CH = (NN + 1023) / 1024;   // 98
    int beg = t * CH;
    int end = beg + CH; if (end > NN) end = NN;
    int tot = 0;
    for (int i = beg; i < end; i++) tot += g_counts[i];
    ssum[t] = tot;
    __syncthreads();
    // Hillis-Steele inclusive scan
    for (int d = 1; d < 1024; d <<= 1) {
        int v = (t >= d) ? ssum[t - d] : 0;
        __syncthreads();
        ssum[t] += v;
        __syncthreads();
    }
    int run = ssum[t] - tot;  // exclusive prefix
    for (int i = beg; i < end; i++) {
        g_row_off[i] = run;
        g_cursor[i]  = run;
        run += g_counts[i];
    }
    if (t == 1023) g_row_off[NN] = ssum[1023];
}

__global__ void fill_kernel(const int* __restrict__ srcp,
                            const int* __restrict__ dstp) {
    int i = blockIdx.x * blockDim.x + threadIdx.x;
    if (i < EE) {
        int d = dstp[i];
        int pos = atomicAdd(&g_cursor[d], 1);
        g_csr_src[pos] = srcp[i];
    }
}

// ---------------- BN stats ----------------
__global__ void zero_stats_kernel() {
    int f = threadIdx.x;
    if (f < DH) { g_sum[f] = 0.0; g_sumsq[f] = 0.0; }
}

__global__ void stats_kernel(const float* __restrict__ h) {
    // 256 threads: f = t%64, row-group r = t/64 (4 rows in flight per block)
    int f = threadIdx.x & 63;
    int r = threadIdx.x >> 6;
    float s = 0.f, q = 0.f;
    for (int n = blockIdx.x * 4 + r; n < NN; n += gridDim.x * 4) {
        float v = h[(size_t)n * DH + f];
        s += v;
        q = fmaf(v, v, q);
    }
    __shared__ float ss[4][DH], sq[4][DH];
    ss[r][f] = s; sq[r][f] = q;
    __syncthreads();
    if (r == 0) {
        float S = ss[0][f] + ss[1][f] + ss[2][f] + ss[3][f];
        float Q = sq[0][f] + sq[1][f] + sq[2][f] + sq[3][f];
        atomicAdd(&g_sum[f], (double)S);
        atomicAdd(&g_sumsq[f], (double)Q);
    }
}

__global__ void finalize_kernel(const float* __restrict__ gamma,
                                const float* __restrict__ beta) {
    int f = threadIdx.x;
    if (f < DH) {
        double mu  = g_sum[f] / (double)NN;
        double var = g_sumsq[f] / (double)NN - mu * mu;
        if (var < 0.0) var = 0.0;
        float inv = rsqrtf((float)var + 1e-5f);
        float a = gamma[f] * inv;
        g_aff_a[f] = a;
        g_aff_b[f] = fmaf(-(float)mu, a, beta[f]);
    }
}

// ---------------- GENConv aggregation: warp per destination node ----------------
// msg = relu(a*h[src]+b) + 1e-7 ; agg = sum(exp(msg)*msg) / sum(exp(msg))
// u = base + agg, base = use_aff ? relu(a*h[n]+b) : h[n]
__global__ void agg_kernel(const float* __restrict__ h,
                           float* __restrict__ u,
                           int use_aff) {
    int gw   = (blockIdx.x * blockDim.x + threadIdx.x) >> 5;
    int lane = threadIdx.x & 31;
    if (gw >= NN) return;
    int f = lane * 2;

    float a0 = 1.f, a1 = 1.f, b0 = 0.f, b1 = 0.f;
    if (use_aff) {
        a0 = g_aff_a[f]; a1 = g_aff_a[f + 1];
        b0 = g_aff_b[f]; b1 = g_aff_b[f + 1];
    }

    int beg = g_row_off[gw];
    int end = g_row_off[gw + 1];

    float s0 = 0.f, s1 = 0.f, w0 = 0.f, w1 = 0.f;
    for (int e = beg; e < end; e++) {
        int src = g_csr_src[e];
        float2 hv = *(const float2*)&h[(size_t)src * DH + f];
        float v0 = fmaf(a0, hv.x, b0);
        float v1 = fmaf(a1, hv.y, b1);
        float m0 = fmaxf(v0, 0.f) + 1e-7f;
        float m1 = fmaxf(v1, 0.f) + 1e-7f;
        float e0 = __expf(m0);
        float e1 = __expf(m1);
        s0 += e0; s1 += e1;
        w0 = fmaf(e0, m0, w0);
        w1 = fmaf(e1, m1, w1);
    }
    float agg0 = (s0 > 0.f) ? w0 / s0 : 0.f;
    float agg1 = (s1 > 0.f) ? w1 / s1 : 0.f;

    float2 hn = *(const float2*)&h[(size_t)gw * DH + f];
    float v0 = fmaf(a0, hn.x, b0);
    float v1 = fmaf(a1, hn.y, b1);
    float base0 = use_aff ? fmaxf(v0, 0.f) : v0;
    float base1 = use_aff ? fmaxf(v1, 0.f) : v1;

    float2 o;
    o.x = base0 + agg0;
    o.y = base1 + agg1;
    *(float2*)&u[(size_t)gw * DH + f] = o;
}

// ---------------- tiled GEMM: out[N,64] = in[N,KDIM] @ W[KDIM,64] + bias (+res) ----------------
template <int KDIM, bool RES>
__global__ void gemm_kernel(const float* __restrict__ in,
                            const float* __restrict__ W,
                            const float* __restrict__ bias,
                            const float* __restrict__ res,
                            float* __restrict__ out) {
    __shared__ float sIn[64 * 64];
    __shared__ float sW[64 * 64];
    const int row0 = blockIdx.x * 64;
    const int tx = threadIdx.x & 15;   // col group (4 cols)
    const int ty = threadIdx.x >> 4;   // row group (4 rows)

    float acc[4][4];
#pragma unroll
    for (int i = 0; i < 4; i++)
#pragma unroll
        for (int j = 0; j < 4; j++) acc[i][j] = 0.f;

    for (int kc = 0; kc < KDIM; kc += 64) {
#pragma unroll
        for (int i = threadIdx.x; i < 1024; i += 256) {
            int r = i >> 4, c4 = i & 15;
            int grow = row0 + r;
            float4 v = make_float4(0.f, 0.f, 0.f, 0.f);
            if (grow < NN) v = *(const float4*)&in[(size_t)grow * KDIM + kc + c4 * 4];
            *(float4*)&sIn[r * 64 + c4 * 4] = v;
            *(float4*)&sW[r * 64 + c4 * 4] = *(const float4*)&W[(size_t)(kc + r) * 64 + c4 * 4];
        }
        __syncthreads();
#pragma unroll
        for (int k = 0; k < 64; k++) {
            float4 wv = *(const float4*)&sW[k * 64 + tx * 4];
            float a0 = sIn[(ty * 4 + 0) * 64 + k];
            float a1 = sIn[(ty * 4 + 1) * 64 + k];
            float a2 = sIn[(ty * 4 + 2) * 64 + k];
            float a3 = sIn[(ty * 4 + 3) * 64 + k];
            acc[0][0] = fmaf(a0, wv.x, acc[0][0]); acc[0][1] = fmaf(a0, wv.y, acc[0][1]);
            acc[0][2] = fmaf(a0, wv.z, acc[0][2]); acc[0][3] = fmaf(a0, wv.w, acc[0][3]);
            acc[1][0] = fmaf(a1, wv.x, acc[1][0]); acc[1][1] = fmaf(a1, wv.y, acc[1][1]);
            acc[1][2] = fmaf(a1, wv.z, acc[1][2]); acc[1][3] = fmaf(a1, wv.w, acc[1][3]);
            acc[2][0] = fmaf(a2, wv.x, acc[2][0]); acc[2][1] = fmaf(a2, wv.y, acc[2][1]);
            acc[2][2] = fmaf(a2, wv.z, acc[2][2]); acc[2][3] = fmaf(a2, wv.w, acc[2][3]);
            acc[3][0] = fmaf(a3, wv.x, acc[3][0]); acc[3][1] = fmaf(a3, wv.y, acc[3][1]);
            acc[3][2] = fmaf(a3, wv.z, acc[3][2]); acc[3][3] = fmaf(a3, wv.w, acc[3][3]);
        }
        __syncthreads();
    }

    float4 bv = *(const float4*)&bias[tx * 4];
#pragma unroll
    for (int r = 0; r < 4; r++) {
        int grow = row0 + ty * 4 + r;
        if (grow < NN) {
            float4 o;
            o.x = acc[r][0] + bv.x; o.y = acc[r][1] + bv.y;
            o.z = acc[r][2] + bv.z; o.w = acc[r][3] + bv.w;
            if (RES) {
                float4 rv = *(const float4*)&res[(size_t)grow * 64 + tx * 4];
                o.x += rv.x; o.y += rv.y; o.z += rv.z; o.w += rv.w;
            }
            *(float4*)&out[(size_t)grow * 64 + tx * 4] = o;
        }
    }
}

// ---------------- predictor: relu(BN(h)) @ W_pred + b_pred -> log_softmax ----------------
__global__ void pred_kernel(const float* __restrict__ h,
                            const float* __restrict__ Wp,
                            const float* __restrict__ bp,
                            float* __restrict__ out) {
    __shared__ float sWp[DH * DOUT];   // 2560 floats
    __shared__ float sh2[8][DH];
    for (int i = threadIdx.x; i < DH * DOUT; i += 256) sWp[i] = Wp[i];
    __syncthreads();

    int warp = threadIdx.x >> 5;
    int lane = threadIdx.x & 31;
    int node = blockIdx.x * 8 + warp;
    if (node >= NN) return;

    int f = lane * 2;
    float2 hv = *(const float2*)&h[(size_t)node * DH + f];
    float v0 = fmaxf(fmaf(g_aff_a[f],     hv.x, g_aff_b[f]),     0.f);
    float v1 = fmaxf(fmaf(g_aff_a[f + 1], hv.y, g_aff_b[f + 1]), 0.f);
    sh2[warp][f]     = v0;
    sh2[warp][f + 1] = v1;
    __syncwarp();

    float acc0 = 0.f, acc1 = 0.f;
#pragma unroll
    for (int k = 0; k < DH; k++) {
        float t = sh2[warp][k];
        acc0 = fmaf(t, sWp[k * DOUT + lane], acc0);
        acc1 = fmaf(t, sWp[k * DOUT + 32 + (lane & 7)], acc1);
    }
    float l0 = acc0 + bp[lane];                                  // cols 0..31
    float l1 = acc1 + ((lane < 8) ? bp[32 + lane] : 0.f);        // cols 32..39 (lane<8)

    float lm = l0;
    if (lane < 8) lm = fmaxf(lm, l1);
#pragma unroll
    for (int o = 16; o; o >>= 1) lm = fmaxf(lm, __shfl_xor_sync(0xffffffffu, lm, o));
    float se = __expf(l0 - lm) + ((lane < 8) ? __expf(l1 - lm) : 0.f);
#pragma unroll
    for (int o = 16; o; o >>= 1) se += __shfl_xor_sync(0xffffffffu, se, o);
    float lse = lm + logf(se);

    out[(size_t)node * DOUT + lane] = l0 - lse;
    if (lane < 8) out[(size_t)node * DOUT + 32 + lane] = l1 - lse;
}

// ---------------- launch ----------------
extern "C" void kernel_launch(void* const* d_in, const int* in_sizes, int n_in,
                              void* d_out, int out_size) {
    const float* x      = (const float*)d_in[0];
    const int*   ei     = (const int*)d_in[1];     // int32! (JAX x64 disabled)
    const float* W_enc  = (const float*)d_in[2];
    const float* b_enc  = (const float*)d_in[3];
    const float* Wg     = (const float*)d_in[4];
    const float* bg     = (const float*)d_in[5];
    const float* gamma  = (const float*)d_in[6];
    const float* beta   = (const float*)d_in[7];
    const float* W_pred = (const float*)d_in[8];
    const float* b_pred = (const float*)d_in[9];
    float*       out    = (float*)d_out;

    const int* srcp = ei;
    const int* dstp = ei + EE;

    float *bufA, *bufB, *bufU;
    cudaGetSymbolAddress((void**)&bufA, g_bufA);
    cudaGetSymbolAddress((void**)&bufB, g_bufB);
    cudaGetSymbolAddress((void**)&bufU, g_bufU);

    const int GB = (NN + 63) / 64;       // gemm blocks
    const int AB = (NN + 7) / 8;         // agg blocks (8 warps/block)
    const int EB = (EE + 255) / 256;

    // CSR build (once per launch)
    zero_counts_kernel<<<(NN + 255) / 256, 256>>>();
    count_kernel<<<EB, 256>>>(dstp);
    scan_kernel<<<1, 1024>>>();
    fill_kernel<<<EB, 256>>>(srcp, dstp);

    // encoder
    gemm_kernel<DIN, false><<<GB, 256>>>(x, W_enc, b_enc, nullptr, bufA);

    // layer 0 (no BN, no residual)
    agg_kernel<<<AB, 256>>>(bufA, bufU, 0);
    gemm_kernel<DH, false><<<GB, 256>>>(bufU, Wg, bg, nullptr, bufB);

    float* h     = bufB;
    float* other = bufA;
    for (int l = 1; l < LL; l++) {
        zero_stats_kernel<<<1, 64>>>();
        stats_kernel<<<256, 256>>>(h);
        finalize_kernel<<<1, 64>>>(gamma + (size_t)(l - 1) * DH, beta + (size_t)(l - 1) * DH);
        agg_kernel<<<AB, 256>>>(h, bufU, 1);
        gemm_kernel<DH, true><<<GB, 256>>>(bufU, Wg + (size_t)l * DH * DH,
                                           bg + (size_t)l * DH, h, other);
        float* tmp = h; h = other; other = tmp;
    }

    // final BN -> relu -> predictor -> log_softmax
    zero_stats_kernel<<<1, 64>>>();
    stats_kernel<<<256, 256>>>(h);
    finalize_kernel<<<1, 64>>>(gamma + (size_t)(LL - 1) * DH, beta + (size_t)(LL - 1) * DH);
    pred_kernel<<<AB, 256>>>(h, W_pred, b_pred, out);
}

// round 3
// speedup vs baseline: 1.0660x; 1.0660x over previous
#include <cuda_runtime.h>
#include <cuda_fp16.h>
#include <math.h>

#define NN 100000
#define EE 1000000
#define DH 64
#define DIN 128
#define DOUT 40
#define LL 7
#define GBLK 1563   // ceil(NN/64)

// ---------------- scratch (static device memory; no allocs) ----------------
__device__ float   g_bufA[(size_t)NN * DH];
__device__ float   g_bufB[(size_t)NN * DH];
__device__ float   g_bufU[(size_t)NN * DH];
__device__ __half2 g_msg[(size_t)NN * (DH / 2)];
__device__ int     g_counts[NN];
__device__ int     g_row_off[NN + 1];
__device__ int     g_cursor[NN];
__device__ int     g_csr_src[EE];
__device__ float   g_psum[GBLK][DH];
__device__ float   g_psq[GBLK][DH];
__device__ float   g_aff_a[DH];
__device__ float   g_aff_b[DH];

// ---------------- CSR build ----------------
__global__ void count_kernel(const int* __restrict__ dstp) {
    int i = blockIdx.x * blockDim.x + threadIdx.x;
    if (i < EE) atomicAdd(&g_counts[dstp[i]], 1);
}

__global__ void scan_kernel() {
    __shared__ int ssum[1024];
    const int t = threadIdx.x;
    const int CH = (NN + 1023) / 1024;   // 98
    int beg = t * CH;
    int end = beg + CH; if (end > NN) end = NN;
    int tot = 0;
    for (int i = beg; i < end; i++) tot += g_counts[i];
    ssum[t] = tot;
    __syncthreads();
    for (int d = 1; d < 1024; d <<= 1) {
        int v = (t >= d) ? ssum[t - d] : 0;
        __syncthreads();
        ssum[t] += v;
        __syncthreads();
    }
    int run = ssum[t] - tot;  // exclusive prefix
    for (int i = beg; i < end; i++) {
        g_row_off[i] = run;
        g_cursor[i]  = run;
        run += g_counts[i];
    }
    if (t == 1023) g_row_off[NN] = ssum[1023];
}

__global__ void fill_kernel(const int* __restrict__ srcp,
                            const int* __restrict__ dstp) {
    int i = blockIdx.x * blockDim.x + threadIdx.x;
    if (i < EE) {
        int d = dstp[i];
        int pos = atomicAdd(&g_cursor[d], 1);
        g_csr_src[pos] = srcp[i];
    }
}

// ---------------- BN finalize: reduce per-block partials -> affine ----------------
__global__ void finalize_kernel(const float* __restrict__ gamma,
                                const float* __restrict__ beta) {
    __shared__ double sS[1024], sQ[1024];
    int t = threadIdx.x;
    int col = t & 63, chunk = t >> 6;  // 16 chunks
    double S = 0.0, Q = 0.0;
    for (int b = chunk; b < GBLK; b += 16) {
        S += (double)g_psum[b][col];
        Q += (double)g_psq[b][col];
    }
    sS[t] = S; sQ[t] = Q;
    __syncthreads();
    if (t < 64) {
        double SS = 0.0, QQ = 0.0;
#pragma unroll
        for (int g2 = 0; g2 < 16; g2++) { SS += sS[g2 * 64 + t]; QQ += sQ[g2 * 64 + t]; }
        double mu  = SS / (double)NN;
        double var = QQ / (double)NN - mu * mu;
        if (var < 0.0) var = 0.0;
        float inv = rsqrtf((float)var + 1e-5f);
        float a = gamma[t] * inv;
        g_aff_a[t] = a;
        g_aff_b[t] = fmaf(-(float)mu, a, beta[t]);
    }
}

// ---------------- message table: m = relu(aff(h)) + eps  (fp16) ----------------
__global__ void msg_build_kernel(const float* __restrict__ h, int use_aff) {
    int i = blockIdx.x * blockDim.x + threadIdx.x;   // one half2 (two features)
    if (i >= NN * (DH / 2)) return;
    int f = (i & 31) * 2;
    float a0 = 1.f, a1 = 1.f, b0 = 0.f, b1 = 0.f;
    if (use_aff) {
        a0 = g_aff_a[f]; a1 = g_aff_a[f + 1];
        b0 = g_aff_b[f]; b1 = g_aff_b[f + 1];
    }
    float2 v = ((const float2*)h)[i];
    float m0 = fmaxf(fmaf(a0, v.x, b0), 0.f) + 1e-7f;
    float m1 = fmaxf(fmaf(a1, v.y, b1), 0.f) + 1e-7f;
    g_msg[i] = __floats2half2_rn(m0, m1);
}

// ---------------- GENConv aggregation: warp per destination node ----------------
// agg = sum(exp(m)*m)/sum(exp(m));  u = base + agg
// base = use_aff ? relu(aff(h[n])) : h[n]
__global__ void agg_kernel(const float* __restrict__ h,
                           float* __restrict__ u,
                           int use_aff) {
    int gw   = (blockIdx.x * blockDim.x + threadIdx.x) >> 5;
    int lane = threadIdx.x & 31;
    if (gw >= NN) return;
    int f = lane * 2;

    int beg = g_row_off[gw];
    int end = g_row_off[gw + 1];

    float s0 = 0.f, s1 = 0.f, w0 = 0.f, w1 = 0.f;
    int e = beg;
    for (; e + 4 <= end; e += 4) {
        int i0 = g_csr_src[e];
        int i1 = g_csr_src[e + 1];
        int i2 = g_csr_src[e + 2];
        int i3 = g_csr_src[e + 3];
        __half2 x0 = g_msg[i0 * 32 + lane];
        __half2 x1 = g_msg[i1 * 32 + lane];
        __half2 x2 = g_msg[i2 * 32 + lane];
        __half2 x3 = g_msg[i3 * 32 + lane];
        float2 v0 = __half22float2(x0);
        float2 v1 = __half22float2(x1);
        float2 v2 = __half22float2(x2);
        float2 v3 = __half22float2(x3);
        float e00 = __expf(v0.x), e01 = __expf(v0.y);
        float e10 = __expf(v1.x), e11 = __expf(v1.y);
        float e20 = __expf(v2.x), e21 = __expf(v2.y);
        float e30 = __expf(v3.x), e31 = __expf(v3.y);
        s0 += e00 + e10 + e20 + e30;
        s1 += e01 + e11 + e21 + e31;
        w0 = fmaf(e00, v0.x, w0); w0 = fmaf(e10, v1.x, w0);
        w0 = fmaf(e20, v2.x, w0); w0 = fmaf(e30, v3.x, w0);
        w1 = fmaf(e01, v0.y, w1); w1 = fmaf(e11, v1.y, w1);
        w1 = fmaf(e21, v2.y, w1); w1 = fmaf(e31, v3.y, w1);
    }
    for (; e < end; e++) {
        int i0 = g_csr_src[e];
        float2 v0 = __half22float2(g_msg[i0 * 32 + lane]);
        float e00 = __expf(v0.x), e01 = __expf(v0.y);
        s0 += e00; s1 += e01;
        w0 = fmaf(e00, v0.x, w0);
        w1 = fmaf(e01, v0.y, w1);
    }
    float agg0 = (s0 > 0.f) ? w0 / s0 : 0.f;
    float agg1 = (s1 > 0.f) ? w1 / s1 : 0.f;

    float2 hn = *(const float2*)&h[(size_t)gw * DH + f];
    float base0, base1;
    if (use_aff) {
        base0 = fmaxf(fmaf(g_aff_a[f],     hn.x, g_aff_b[f]),     0.f);
        base1 = fmaxf(fmaf(g_aff_a[f + 1], hn.y, g_aff_b[f + 1]), 0.f);
    } else {
        base0 = hn.x;
        base1 = hn.y;
    }

    float2 o;
    o.x = base0 + agg0;
    o.y = base1 + agg1;
    *(float2*)&u[(size_t)gw * DH + f] = o;
}

// ---- tiled GEMM: out[N,64] = in[N,KDIM] @ W[KDIM,64] + bias (+res) (+stats) ----
template <int KDIM, bool RES, bool STATS>
__global__ void gemm_kernel(const float* __restrict__ in,
                            const float* __restrict__ W,
                            const float* __restrict__ bias,
                            const float* __restrict__ res,
                            float* __restrict__ out) {
    __shared__ float sIn[64 * 64];
    __shared__ float sW[64 * 64];
    const int row0 = blockIdx.x * 64;
    const int tx = threadIdx.x & 15;   // col group (4 cols)
    const int ty = threadIdx.x >> 4;   // row group (4 rows)

    float acc[4][4];
#pragma unroll
    for (int i = 0; i < 4; i++)
#pragma unroll
        for (int j = 0; j < 4; j++) acc[i][j] = 0.f;

    for (int kc = 0; kc < KDIM; kc += 64) {
#pragma unroll
        for (int i = threadIdx.x; i < 1024; i += 256) {
            int r = i >> 4, c4 = i & 15;
            int grow = row0 + r;
            float4 v = make_float4(0.f, 0.f, 0.f, 0.f);
            if (grow < NN) v = *(const float4*)&in[(size_t)grow * KDIM + kc + c4 * 4];
            *(float4*)&sIn[r * 64 + c4 * 4] = v;
            *(float4*)&sW[r * 64 + c4 * 4] = *(const float4*)&W[(size_t)(kc + r) * 64 + c4 * 4];
        }
        __syncthreads();
#pragma unroll
        for (int k = 0; k < 64; k++) {
            float4 wv = *(const float4*)&sW[k * 64 + tx * 4];
            float a0 = sIn[(ty * 4 + 0) * 64 + k];
            float a1 = sIn[(ty * 4 + 1) * 64 + k];
            float a2 = sIn[(ty * 4 + 2) * 64 + k];
            float a3 = sIn[(ty * 4 + 3) * 64 + k];
            acc[0][0] = fmaf(a0, wv.x, acc[0][0]); acc[0][1] = fmaf(a0, wv.y, acc[0][1]);
            acc[0][2] = fmaf(a0, wv.z, acc[0][2]); acc[0][3] = fmaf(a0, wv.w, acc[0][3]);
            acc[1][0] = fmaf(a1, wv.x, acc[1][0]); acc[1][1] = fmaf(a1, wv.y, acc[1][1]);
            acc[1][2] = fmaf(a1, wv.z, acc[1][2]); acc[1][3] = fmaf(a1, wv.w, acc[1][3]);
            acc[2][0] = fmaf(a2, wv.x, acc[2][0]); acc[2][1] = fmaf(a2, wv.y, acc[2][1]);
            acc[2][2] = fmaf(a2, wv.z, acc[2][2]); acc[2][3] = fmaf(a2, wv.w, acc[2][3]);
            acc[3][0] = fmaf(a3, wv.x, acc[3][0]); acc[3][1] = fmaf(a3, wv.y, acc[3][1]);
            acc[3][2] = fmaf(a3, wv.z, acc[3][2]); acc[3][3] = fmaf(a3, wv.w, acc[3][3]);
        }
        __syncthreads();
    }

    float4 bv = *(const float4*)&bias[tx * 4];
    float s[4] = {0.f, 0.f, 0.f, 0.f};
    float q[4] = {0.f, 0.f, 0.f, 0.f};
#pragma unroll
    for (int r = 0; r < 4; r++) {
        int grow = row0 + ty * 4 + r;
        if (grow < NN) {
            float4 o;
            o.x = acc[r][0] + bv.x; o.y = acc[r][1] + bv.y;
            o.z = acc[r][2] + bv.z; o.w = acc[r][3] + bv.w;
            if (RES) {
                float4 rv = *(const float4*)&res[(size_t)grow * 64 + tx * 4];
                o.x += rv.x; o.y += rv.y; o.z += rv.z; o.w += rv.w;
            }
            *(float4*)&out[(size_t)grow * 64 + tx * 4] = o;
            if (STATS) {
                s[0] += o.x; q[0] = fmaf(o.x, o.x, q[0]);
                s[1] += o.y; q[1] = fmaf(o.y, o.y, q[1]);
                s[2] += o.z; q[2] = fmaf(o.z, o.z, q[2]);
                s[3] += o.w; q[3] = fmaf(o.w, o.w, q[3]);
            }
        }
    }
    if (STATS) {
        // reuse smem for per-block column reduction (all compute done)
#pragma unroll
        for (int c = 0; c < 4; c++) {
            sIn[ty * 64 + tx * 4 + c] = s[c];
            sW [ty * 64 + tx * 4 + c] = q[c];
        }
        __syncthreads();
        if (threadIdx.x < 64) {
            float S = 0.f, Q = 0.f;
#pragma unroll
            for (int g2 = 0; g2 < 16; g2++) {
                S += sIn[g2 * 64 + threadIdx.x];
                Q += sW [g2 * 64 + threadIdx.x];
            }
            g_psum[blockIdx.x][threadIdx.x] = S;
            g_psq [blockIdx.x][threadIdx.x] = Q;
        }
    }
}

// ---------------- predictor: relu(BN(h)) @ W_pred + b_pred -> log_softmax ----------------
__global__ void pred_kernel(const float* __restrict__ h,
                            const float* __restrict__ Wp,
                            const float* __restrict__ bp,
                            float* __restrict__ out) {
    __shared__ float sWp[DH * DOUT];
    __shared__ float sh2[8][DH];
    for (int i = threadIdx.x; i < DH * DOUT; i += 256) sWp[i] = Wp[i];
    __syncthreads();

    int warp = threadIdx.x >> 5;
    int lane = threadIdx.x & 31;
    int node = blockIdx.x * 8 + warp;
    if (node >= NN) return;

    int f = lane * 2;
    float2 hv = *(const float2*)&h[(size_t)node * DH + f];
    float v0 = fmaxf(fmaf(g_aff_a[f],     hv.x, g_aff_b[f]),     0.f);
    float v1 = fmaxf(fmaf(g_aff_a[f + 1], hv.y, g_aff_b[f + 1]), 0.f);
    sh2[warp][f]     = v0;
    sh2[warp][f + 1] = v1;
    __syncwarp();

    float acc0 = 0.f, acc1 = 0.f;
#pragma unroll
    for (int k = 0; k < DH; k++) {
        float t = sh2[warp][k];
        acc0 = fmaf(t, sWp[k * DOUT + lane], acc0);
        acc1 = fmaf(t, sWp[k * DOUT + 32 + (lane & 7)], acc1);
    }
    float l0 = acc0 + bp[lane];
    float l1 = acc1 + ((lane < 8) ? bp[32 + lane] : 0.f);

    float lm = l0;
    if (lane < 8) lm = fmaxf(lm, l1);
#pragma unroll
    for (int o = 16; o; o >>= 1) lm = fmaxf(lm, __shfl_xor_sync(0xffffffffu, lm, o));
    float se = __expf(l0 - lm) + ((lane < 8) ? __expf(l1 - lm) : 0.f);
#pragma unroll
    for (int o = 16; o; o >>= 1) se += __shfl_xor_sync(0xffffffffu, se, o);
    float lse = lm + logf(se);

    out[(size_t)node * DOUT + lane] = l0 - lse;
    if (lane < 8) out[(size_t)node * DOUT + 32 + lane] = l1 - lse;
}

// ---------------- launch ----------------
extern "C" void kernel_launch(void* const* d_in, const int* in_sizes, int n_in,
                              void* d_out, int out_size) {
    const float* x      = (const float*)d_in[0];
    const int*   ei     = (const int*)d_in[1];     // int32 (JAX x64 disabled)
    const float* W_enc  = (const float*)d_in[2];
    const float* b_enc  = (const float*)d_in[3];
    const float* Wg     = (const float*)d_in[4];
    const float* bg     = (const float*)d_in[5];
    const float* gamma  = (const float*)d_in[6];
    const float* beta   = (const float*)d_in[7];
    const float* W_pred = (const float*)d_in[8];
    const float* b_pred = (const float*)d_in[9];
    float*       out    = (float*)d_out;

    const int* srcp = ei;
    const int* dstp = ei + EE;

    float *bufA, *bufB, *bufU;
    void* cnts;
    cudaGetSymbolAddress((void**)&bufA, g_bufA);
    cudaGetSymbolAddress((void**)&bufB, g_bufB);
    cudaGetSymbolAddress((void**)&bufU, g_bufU);
    cudaGetSymbolAddress(&cnts, g_counts);

    const int AB = (NN + 7) / 8;            // agg/pred blocks (8 warps/block)
    const int EB = (EE + 255) / 256;
    const int MB = (NN * (DH / 2) + 255) / 256;  // msg_build blocks

    // CSR build (once per launch)
    cudaMemsetAsync(cnts, 0, (size_t)NN * sizeof(int));
    count_kernel<<<EB, 256>>>(dstp);
    scan_kernel<<<1, 1024>>>();
    fill_kernel<<<EB, 256>>>(srcp, dstp);

    // encoder (no stats needed)
    gemm_kernel<DIN, false, false><<<GBLK, 256>>>(x, W_enc, b_enc, nullptr, bufA);

    // layer 0 (identity affine, no residual; gemm collects stats for BN of layer 1)
    msg_build_kernel<<<MB, 256>>>(bufA, 0);
    agg_kernel<<<AB, 256>>>(bufA, bufU, 0);
    gemm_kernel<DH, false, true><<<GBLK, 256>>>(bufU, Wg, bg, nullptr, bufB);

    float* h     = bufB;
    float* other = bufA;
    for (int l = 1; l < LL; l++) {
        finalize_kernel<<<1, 1024>>>(gamma + (size_t)(l - 1) * DH, beta + (size_t)(l - 1) * DH);
        msg_build_kernel<<<MB, 256>>>(h, 1);
        agg_kernel<<<AB, 256>>>(h, bufU, 1);
        gemm_kernel<DH, true, true><<<GBLK, 256>>>(bufU, Wg + (size_t)l * DH * DH,
                                                   bg + (size_t)l * DH, h, other);
        float* tmp = h; h = other; other = tmp;
    }

    // final BN -> relu -> predictor -> log_softmax
    finalize_kernel<<<1, 1024>>>(gamma + (size_t)(LL - 1) * DH, beta + (size_t)(LL - 1) * DH);
    pred_kernel<<<AB, 256>>>(h, W_pred, b_pred, out);
}